// round 14
// baseline (speedup 1.0000x reference)
#include <cuda_runtime.h>
#include <cuda_fp16.h>
#include <mma.h>
#include <math.h>

using namespace nvcuda;

#define NN 100000
#define NE 1600000
#define NV 15000
#define DD 128
#define NG 16
#define NPAD 100352                 // 98 * 1024
#define NSCB 98                     // scan blocks (1024 counts each)

// ---------------- device scratch (static: no allocations allowed) ------------
__device__ int      g_off[NPAD + 4];
__device__ int      g_cursor[NPAD + 4];
__device__ int      g_bsum[NSCB];
__device__ int2     g_meta[NE];            // {(wid<<17)|src, bits(w*norm[src])}
__device__ __half   g_Ph[NV * DD];         // embeds @ W0 fp16 (L2-resident)
__device__ unsigned g_H0q[NN * 32];        // layer-1 output int8 rows (128 B/row)
__device__ float    g_scale[NN];           // per-row dequant scale
__device__ __half   g_S1h[(NN + 64) * DD]; // N*A*N*H0 fp16 (padded for TC tiles)
__device__ __half   g_W0h[DD * DD];
__device__ __half   g_W1h[DD * DD];
__device__ float    g_pool[NG * DD];       // per-graph max (relu>=0 -> int cmp)

// ---------------- helpers ----------------------------------------------------
__device__ __forceinline__ void split_h2(float2 raw, float2& f0, float2& f1) {
    __half2 h0 = *reinterpret_cast<__half2*>(&raw.x);
    __half2 h1 = *reinterpret_cast<__half2*>(&raw.y);
    f0 = __half22float2(h0);
    f1 = __half22float2(h1);
}

// ---------------- 0: zero + W conversions ------------------------------------
__global__ void k_zero(const float* __restrict__ W0, const float* __restrict__ W1) {
    int i = blockIdx.x * 256 + threadIdx.x;
    if (i < NPAD + 4) g_off[i] = 0;
    if (i < NG * DD) g_pool[i] = 0.0f;
    if (i < DD * DD) {
        g_W0h[i] = __float2half(W0[i]);
        g_W1h[i] = __float2half(W1[i]);
    }
}

// ---------------- 1: histogram -----------------------------------------------
__global__ void k_hist(const int* __restrict__ edst) {
    int e = blockIdx.x * 256 + threadIdx.x;
    if (e < NE) atomicAdd(&g_off[edst[e]], 1);
}

// ---------------- 2: per-chunk sums ------------------------------------------
__global__ void k_scan1() {
    __shared__ int sm[256];
    int b = blockIdx.x, t = threadIdx.x;
    int4 c = ((const int4*)g_off)[b * 256 + t];
    int s = c.x + c.y + c.z + c.w;
    sm[t] = s;
    __syncthreads();
    for (int off = 128; off > 0; off >>= 1) {
        if (t < off) sm[t] += sm[t + off];
        __syncthreads();
    }
    if (t == 0) g_bsum[b] = sm[0];
}

// ---------------- 3: local scan + inline block-offset reduction --------------
__global__ void k_scan3() {
    __shared__ int sm[256];
    __shared__ int red[128];
    __shared__ int s_base;
    int b = blockIdx.x, t = threadIdx.x;

    if (t < 128) red[t] = (t < b) ? g_bsum[t] : 0;    // b <= 97 < 128
    __syncthreads();
    if (t < 64) red[t] += red[t + 64];
    __syncthreads();
    if (t < 32) {
        int v = red[t] + red[t + 32];
#pragma unroll
        for (int o = 16; o > 0; o >>= 1) v += __shfl_down_sync(0xffffffffu, v, o);
        if (t == 0) s_base = v;
    }

    int4 c = ((const int4*)g_off)[b * 256 + t];
    int s = c.x + c.y + c.z + c.w;
    sm[t] = s;
    __syncthreads();
    for (int off = 1; off < 256; off <<= 1) {
        int u = (t >= off) ? sm[t - off] : 0;
        __syncthreads();
        sm[t] += u;
        __syncthreads();
    }
    int base = s_base + sm[t] - s;
    int4 o;
    o.x = base;
    o.y = base + c.x;
    o.z = o.y + c.y;
    o.w = o.z + c.z;
    ((int4*)g_off)[b * 256 + t] = o;
    ((int4*)g_cursor)[b * 256 + t] = o;
}

// ---------------- 4: scatter (standalone, low-footprint) ---------------------
__global__ void k_scatter(const int* __restrict__ esrc, const int* __restrict__ edst,
                          const float* __restrict__ ew, const float* __restrict__ norm,
                          const int* __restrict__ word_ids) {
    int e = blockIdx.x * 256 + threadIdx.x;
    if (e >= NE) return;
    int d = edst[e];
    int s = esrc[e];
    int pos = atomicAdd(&g_cursor[d], 1);
    float wn = ew[e] * __ldg(&norm[s]);
    int packed = s | (__ldg(&word_ids[s]) << 17);   // src < 2^17, wid < 2^14
    g_meta[pos] = make_int2(packed, __float_as_int(wn));
}

// ---------------- 5: gemm0 -- Ph = half(emb @ W0), inline fp32->fp16 ---------
__global__ __launch_bounds__(128) void gemm0_k(const float* __restrict__ emb) {
    __shared__ __half Ah[64 * DD];   // 16 KB
    __shared__ float St[64 * 32];    // 8 KB staging
    int rb = blockIdx.x * 64;
    for (int i = threadIdx.x; i < 64 * DD; i += 128) {
        int row = rb + (i >> 7);
        Ah[i] = (row < NV) ? __float2half(emb[row * DD + (i & 127)]) : __half(0.f);
    }
    __syncthreads();

    int warp = threadIdx.x >> 5;
    wmma::fragment<wmma::accumulator, 16, 16, 16, float> acc[8];
#pragma unroll
    for (int n = 0; n < 8; n++) wmma::fill_fragment(acc[n], 0.0f);
#pragma unroll
    for (int k = 0; k < 8; k++) {
        wmma::fragment<wmma::matrix_a, 16, 16, 16, __half, wmma::row_major> af;
        wmma::load_matrix_sync(af, Ah + (warp * 16) * DD + k * 16, DD);
#pragma unroll
        for (int n = 0; n < 8; n++) {
            wmma::fragment<wmma::matrix_b, 16, 16, 16, __half, wmma::row_major> bf;
            wmma::load_matrix_sync(bf, g_W0h + (k * 16) * DD + n * 16, DD);
            wmma::mma_sync(acc[n], af, bf, acc[n]);
        }
    }
    __syncthreads();
#pragma unroll
    for (int n = 0; n < 8; n += 2) {
        wmma::store_matrix_sync(&St[warp * 16 * 32 + 0],  acc[n],     32, wmma::mem_row_major);
        wmma::store_matrix_sync(&St[warp * 16 * 32 + 16], acc[n + 1], 32, wmma::mem_row_major);
        __syncwarp();
        int lane = threadIdx.x & 31;
#pragma unroll
        for (int r = 0; r < 16; r++) {
            int row = rb + warp * 16 + r;
            if (row < NV) {
                float v = St[warp * 16 * 32 + r * 32 + lane];
                g_Ph[row * DD + n * 16 + lane] = __float2half(v);
            }
        }
        __syncwarp();
    }
}

// ---------------- 6: agg0 (warp/node; fp16 gathers; int8+scale output) -------
// acc = sum wn * Ph[wid];  H0 = relu(acc*norm[dst] + b0)  ->  int8 row + scale
__global__ __launch_bounds__(256) void agg0_k(const float* __restrict__ norm,
                                              const float* __restrict__ bias) {
    int node = (blockIdx.x * 256 + threadIdx.x) >> 5;
    if (node >= NN) return;
    int lane = threadIdx.x & 31;
    int beg = g_off[node], end = g_off[node + 1];
    const float2* tbl = (const float2*)g_Ph;

    float ax = 0.f, ay = 0.f, az = 0.f, aw = 0.f;
    int e = beg;
    for (; e + 8 <= end; e += 8) {
        int2 m[8];
#pragma unroll
        for (int j = 0; j < 8; j++) m[j] = __ldg(g_meta + e + j);
        float2 raw[8];
#pragma unroll
        for (int j = 0; j < 8; j++)
            raw[j] = __ldg(tbl + ((unsigned)m[j].x >> 17) * 32 + lane);
#pragma unroll
        for (int j = 0; j < 8; j++) {
            float c = __int_as_float(m[j].y);
            float2 f0, f1; split_h2(raw[j], f0, f1);
            ax = fmaf(c, f0.x, ax); ay = fmaf(c, f0.y, ay);
            az = fmaf(c, f1.x, az); aw = fmaf(c, f1.y, aw);
        }
    }
    for (; e < end; e++) {
        int2 m = __ldg(g_meta + e);
        float2 raw = __ldg(tbl + ((unsigned)m.x >> 17) * 32 + lane);
        float c = __int_as_float(m.y);
        float2 f0, f1; split_h2(raw, f0, f1);
        ax = fmaf(c, f0.x, ax); ay = fmaf(c, f0.y, ay);
        az = fmaf(c, f1.x, az); aw = fmaf(c, f1.y, aw);
    }
    float nd = __ldg(norm + node);
    float4 b = __ldg((const float4*)bias + lane);
    float rx = fmaxf(fmaf(ax, nd, b.x), 0.f);
    float ry = fmaxf(fmaf(ay, nd, b.y), 0.f);
    float rz = fmaxf(fmaf(az, nd, b.z), 0.f);
    float rw = fmaxf(fmaf(aw, nd, b.w), 0.f);

    // per-row max over all 128 features (warp reduction; full warp guaranteed)
    float m4 = fmaxf(fmaxf(rx, ry), fmaxf(rz, rw));
#pragma unroll
    for (int o = 16; o > 0; o >>= 1) m4 = fmaxf(m4, __shfl_xor_sync(0xffffffffu, m4, o));

    float inv = (m4 > 0.f) ? (127.0f / m4) : 0.f;
    int q0 = __float2int_rn(rx * inv);
    int q1 = __float2int_rn(ry * inv);
    int q2 = __float2int_rn(rz * inv);
    int q3 = __float2int_rn(rw * inv);
    unsigned packed = (unsigned)q0 | ((unsigned)q1 << 8) |
                      ((unsigned)q2 << 16) | ((unsigned)q3 << 24);
    g_H0q[node * 32 + lane] = packed;
    if (lane == 0) g_scale[node] = m4 * (1.0f / 127.0f);
}

// ---------------- 7: agg1 (warp/node; int8 gathers) --------------------------
// acc = sum wn * scale[src] * q[src];  S1h = half(acc * norm[dst])
__global__ __launch_bounds__(256) void agg1_k(const float* __restrict__ norm) {
    int node = (blockIdx.x * 256 + threadIdx.x) >> 5;
    if (node >= NN) return;
    int lane = threadIdx.x & 31;
    int beg = g_off[node], end = g_off[node + 1];

    float ax = 0.f, ay = 0.f, az = 0.f, aw = 0.f;
    int e = beg;
    for (; e + 8 <= end; e += 8) {
        int2 m[8];
#pragma unroll
        for (int j = 0; j < 8; j++) m[j] = __ldg(g_meta + e + j);
        unsigned r[8]; float sc[8];
#pragma unroll
        for (int j = 0; j < 8; j++) {
            int idx = m[j].x & 0x1FFFF;
            r[j]  = __ldg(&g_H0q[idx * 32 + lane]);
            sc[j] = __ldg(&g_scale[idx]);          // broadcast (same addr all lanes)
        }
#pragma unroll
        for (int j = 0; j < 8; j++) {
            float c = __int_as_float(m[j].y) * sc[j];
            ax = fmaf(c, (float)( r[j]        & 0xFF), ax);
            ay = fmaf(c, (float)((r[j] >> 8)  & 0xFF), ay);
            az = fmaf(c, (float)((r[j] >> 16) & 0xFF), az);
            aw = fmaf(c, (float)( r[j] >> 24        ), aw);
        }
    }
    for (; e < end; e++) {
        int2 m = __ldg(g_meta + e);
        int idx = m.x & 0x1FFFF;
        unsigned r = __ldg(&g_H0q[idx * 32 + lane]);
        float c = __int_as_float(m.y) * __ldg(&g_scale[idx]);
        ax = fmaf(c, (float)( r        & 0xFF), ax);
        ay = fmaf(c, (float)((r >> 8)  & 0xFF), ay);
        az = fmaf(c, (float)((r >> 16) & 0xFF), az);
        aw = fmaf(c, (float)( r >> 24        ), aw);
    }
    float nd = __ldg(norm + node);
    float2 outp;
    *reinterpret_cast<__half2*>(&outp.x) = __floats2half2_rn(ax * nd, ay * nd);
    *reinterpret_cast<__half2*>(&outp.y) = __floats2half2_rn(az * nd, aw * nd);
    ((float2*)g_S1h)[node * 32 + lane] = outp;
}

// ---------------- 8: gemm1 (tensor core) + bias/relu/max-pool ----------------
__global__ __launch_bounds__(128) void gemm1_k(const float* __restrict__ bias,
                                               const int* __restrict__ gid) {
    __shared__ float sm[64][DD];
    int warp = threadIdx.x >> 5;
    int rb = blockIdx.x * 64;
    int row0 = rb + warp * 16;

    wmma::fragment<wmma::accumulator, 16, 16, 16, float> acc[8];
#pragma unroll
    for (int n = 0; n < 8; n++) wmma::fill_fragment(acc[n], 0.0f);

#pragma unroll
    for (int k = 0; k < 8; k++) {
        wmma::fragment<wmma::matrix_a, 16, 16, 16, __half, wmma::row_major> af;
        wmma::load_matrix_sync(af, g_S1h + row0 * DD + k * 16, DD);
#pragma unroll
        for (int n = 0; n < 8; n++) {
            wmma::fragment<wmma::matrix_b, 16, 16, 16, __half, wmma::row_major> bf;
            wmma::load_matrix_sync(bf, g_W1h + (k * 16) * DD + n * 16, DD);
            wmma::mma_sync(acc[n], af, bf, acc[n]);
        }
    }
#pragma unroll
    for (int n = 0; n < 8; n++)
        wmma::store_matrix_sync(&sm[warp * 16][n * 16], acc[n], DD, wmma::mem_row_major);
    __syncthreads();

    int col = threadIdx.x;
    float bv = __ldg(bias + col);
    int gfirst = __ldg(gid + rb);
    int lastrow = rb + 63; if (lastrow >= NN) lastrow = NN - 1;
    int glast = __ldg(gid + lastrow);
    if (gfirst == glast) {
        float m = 0.0f;
#pragma unroll 4
        for (int r = 0; r < 64; r++) {
            if (rb + r < NN)
                m = fmaxf(m, fmaxf(sm[r][col] + bv, 0.0f));
        }
        atomicMax((int*)&g_pool[gfirst * DD + col], __float_as_int(m));
    } else {
        for (int r = 0; r < 64; r++) {
            int row = rb + r;
            if (row < NN) {
                int gg = __ldg(gid + row);
                float v = fmaxf(sm[r][col] + bv, 0.0f);
                atomicMax((int*)&g_pool[gg * DD + col], __float_as_int(v));
            }
        }
    }
}

// ---------------- 9: head ----------------------------------------------------
__global__ void k_final(const float* __restrict__ Wout, const float* __restrict__ bout,
                        const float* __restrict__ y, float* __restrict__ out,
                        int out_size) {
    __shared__ float s_loss[NG];
    __shared__ float s_pred[NG];
    int warp = threadIdx.x >> 5;
    int lane = threadIdx.x & 31;
    if (warp < NG) {
        float4 gv = ((const float4*)g_pool)[warp * 32 + lane];
        float4 wv = __ldg((const float4*)Wout + lane);
        float d = gv.x * wv.x + gv.y * wv.y + gv.z * wv.z + gv.w * wv.w;
#pragma unroll
        for (int o = 16; o > 0; o >>= 1) d += __shfl_xor_sync(0xffffffffu, d, o);
        if (lane == 0) {
            float z = d + __ldg(bout);
            float yd = __ldg(y + warp);
            s_loss[warp] = fmaxf(z, 0.f) - z * yd + log1pf(expf(-fabsf(z)));
            s_pred[warp] = 1.f / (1.f + expf(-z));
        }
    }
    __syncthreads();
    if (threadIdx.x == 0) {
        float L = 0.f;
        for (int i = 0; i < NG; i++) L += s_loss[i];
        L *= (1.f / NG);
        if (out_size >= NG + 1) {
            out[0] = L;
            for (int i = 0; i < NG; i++) out[1 + i] = s_pred[i];
            for (int i = NG + 1; i < out_size; i++) out[i] = 0.f;
        } else if (out_size == NG) {
            for (int i = 0; i < NG; i++) out[i] = s_pred[i];
        } else {
            out[0] = L;
        }
    }
}

// ---------------- launch -----------------------------------------------------
extern "C" void kernel_launch(void* const* d_in, const int* in_sizes, int n_in,
                              void* d_out, int out_size) {
    const int*   word_ids = (const int*)d_in[0];
    const int*   esrc     = (const int*)d_in[1];
    const int*   edst     = (const int*)d_in[2];
    const float* ew       = (const float*)d_in[3];
    const float* norm     = (const float*)d_in[4];
    const int*   gid      = (const int*)d_in[5];
    const float* y        = (const float*)d_in[6];
    const float* emb      = (const float*)d_in[7];
    const float* W0       = (const float*)d_in[8];
    const float* b0       = (const float*)d_in[9];
    const float* W1       = (const float*)d_in[10];
    const float* b1       = (const float*)d_in[11];
    const float* Wout     = (const float*)d_in[12];
    const float* bout     = (const float*)d_in[13];
    float* out = (float*)d_out;

    k_zero   <<<(NPAD + 4 + 255) / 256, 256>>>(W0, W1);
    k_hist   <<<(NE + 255) / 256, 256>>>(edst);
    k_scan1  <<<NSCB, 256>>>();
    k_scan3  <<<NSCB, 256>>>();
    k_scatter<<<(NE + 255) / 256, 256>>>(esrc, edst, ew, norm, word_ids);
    gemm0_k  <<<(NV + 63) / 64, 128>>>(emb);

    agg0_k   <<<(NN + 7) / 8, 256>>>(norm, b0);
    agg1_k   <<<(NN + 7) / 8, 256>>>(norm);
    gemm1_k  <<<(NN + 63) / 64, 128>>>(b1, gid);

    k_final  <<<1, 512>>>(Wout, bout, y, out, out_size);
}

// round 15
// speedup vs baseline: 1.0517x; 1.0517x over previous
#include <cuda_runtime.h>
#include <cuda_fp16.h>
#include <mma.h>
#include <math.h>

using namespace nvcuda;

#define NN 100000
#define NE 1600000
#define NV 15000
#define DD 128
#define NG 16
#define NPAD 100352                 // 98 * 1024
#define NSCB 98                     // scan blocks (1024 counts each)

// ---------------- device scratch (static: no allocations allowed) ------------
__device__ int    g_off[NPAD + 4];
__device__ int    g_cursor[NPAD + 4];
__device__ int    g_bsum[NSCB];
__device__ int2   g_meta[NE];              // {(wid<<17)|src, bits(w*norm[src])}
__device__ __half g_Ph[NV * DD];           // embeds @ W0 fp16 (L2-resident)
__device__ __half g_H0h[NN * DD];          // layer-1 output fp16
__device__ __half g_S1h[(NN + 64) * DD];   // N*A*N*H0 fp16 (padded for TC tiles)
__device__ __half g_W0h[DD * DD];
__device__ __half g_W1h[DD * DD];
__device__ float  g_pool[NG * DD];         // per-graph max (relu>=0 -> int cmp)

// ---------------- helpers ----------------------------------------------------
__device__ __forceinline__ void split_h2(float2 raw, float2& f0, float2& f1) {
    __half2 h0 = *reinterpret_cast<__half2*>(&raw.x);
    __half2 h1 = *reinterpret_cast<__half2*>(&raw.y);
    f0 = __half22float2(h0);
    f1 = __half22float2(h1);
}

// ---------------- 0: zero + W conversions ------------------------------------
__global__ void k_zero(const float* __restrict__ W0, const float* __restrict__ W1) {
    int i = blockIdx.x * 256 + threadIdx.x;
    if (i < NPAD + 4) g_off[i] = 0;
    if (i < NG * DD) g_pool[i] = 0.0f;
    if (i < DD * DD) {
        g_W0h[i] = __float2half(W0[i]);
        g_W1h[i] = __float2half(W1[i]);
    }
}

// ---------------- 1: histogram -----------------------------------------------
__global__ void k_hist(const int* __restrict__ edst) {
    int e = blockIdx.x * 256 + threadIdx.x;
    if (e < NE) atomicAdd(&g_off[edst[e]], 1);
}

// ---------------- 2: per-chunk sums ------------------------------------------
__global__ void k_scan1() {
    __shared__ int sm[256];
    int b = blockIdx.x, t = threadIdx.x;
    int4 c = ((const int4*)g_off)[b * 256 + t];
    int s = c.x + c.y + c.z + c.w;
    sm[t] = s;
    __syncthreads();
    for (int off = 128; off > 0; off >>= 1) {
        if (t < off) sm[t] += sm[t + off];
        __syncthreads();
    }
    if (t == 0) g_bsum[b] = sm[0];
}

// ---------------- 3: local scan + inline block-offset reduction --------------
__global__ void k_scan3() {
    __shared__ int sm[256];
    __shared__ int red[128];
    __shared__ int s_base;
    int b = blockIdx.x, t = threadIdx.x;

    if (t < 128) red[t] = (t < b) ? g_bsum[t] : 0;    // b <= 97 < 128
    __syncthreads();
    if (t < 64) red[t] += red[t + 64];
    __syncthreads();
    if (t < 32) {
        int v = red[t] + red[t + 32];
#pragma unroll
        for (int o = 16; o > 0; o >>= 1) v += __shfl_down_sync(0xffffffffu, v, o);
        if (t == 0) s_base = v;
    }

    int4 c = ((const int4*)g_off)[b * 256 + t];
    int s = c.x + c.y + c.z + c.w;
    sm[t] = s;
    __syncthreads();
    for (int off = 1; off < 256; off <<= 1) {
        int u = (t >= off) ? sm[t - off] : 0;
        __syncthreads();
        sm[t] += u;
        __syncthreads();
    }
    int base = s_base + sm[t] - s;
    int4 o;
    o.x = base;
    o.y = base + c.x;
    o.z = o.y + c.y;
    o.w = o.z + c.z;
    ((int4*)g_off)[b * 256 + t] = o;
    ((int4*)g_cursor)[b * 256 + t] = o;
}

// ---------------- 4: scatter (standalone, low-footprint) ---------------------
__global__ void k_scatter(const int* __restrict__ esrc, const int* __restrict__ edst,
                          const float* __restrict__ ew, const float* __restrict__ norm,
                          const int* __restrict__ word_ids) {
    int e = blockIdx.x * 256 + threadIdx.x;
    if (e >= NE) return;
    int d = edst[e];
    int s = esrc[e];
    int pos = atomicAdd(&g_cursor[d], 1);
    float wn = ew[e] * __ldg(&norm[s]);
    int packed = s | (__ldg(&word_ids[s]) << 17);   // src < 2^17, wid < 2^14
    g_meta[pos] = make_int2(packed, __float_as_int(wn));
}

// ---------------- 5: gemm0 -- Ph = half(emb @ W0), inline fp32->fp16 ---------
__global__ __launch_bounds__(128) void gemm0_k(const float* __restrict__ emb) {
    __shared__ __half Ah[64 * DD];   // 16 KB
    __shared__ float St[64 * 32];    // 8 KB staging
    int rb = blockIdx.x * 64;
    for (int i = threadIdx.x; i < 64 * DD; i += 128) {
        int row = rb + (i >> 7);
        Ah[i] = (row < NV) ? __float2half(emb[row * DD + (i & 127)]) : __half(0.f);
    }
    __syncthreads();

    int warp = threadIdx.x >> 5;
    wmma::fragment<wmma::accumulator, 16, 16, 16, float> acc[8];
#pragma unroll
    for (int n = 0; n < 8; n++) wmma::fill_fragment(acc[n], 0.0f);
#pragma unroll
    for (int k = 0; k < 8; k++) {
        wmma::fragment<wmma::matrix_a, 16, 16, 16, __half, wmma::row_major> af;
        wmma::load_matrix_sync(af, Ah + (warp * 16) * DD + k * 16, DD);
#pragma unroll
        for (int n = 0; n < 8; n++) {
            wmma::fragment<wmma::matrix_b, 16, 16, 16, __half, wmma::row_major> bf;
            wmma::load_matrix_sync(bf, g_W0h + (k * 16) * DD + n * 16, DD);
            wmma::mma_sync(acc[n], af, bf, acc[n]);
        }
    }
    __syncthreads();
#pragma unroll
    for (int n = 0; n < 8; n += 2) {
        wmma::store_matrix_sync(&St[warp * 16 * 32 + 0],  acc[n],     32, wmma::mem_row_major);
        wmma::store_matrix_sync(&St[warp * 16 * 32 + 16], acc[n + 1], 32, wmma::mem_row_major);
        __syncwarp();
        int lane = threadIdx.x & 31;
#pragma unroll
        for (int r = 0; r < 16; r++) {
            int row = rb + warp * 16 + r;
            if (row < NV) {
                float v = St[warp * 16 * 32 + r * 32 + lane];
                g_Ph[row * DD + n * 16 + lane] = __float2half(v);
            }
        }
        __syncwarp();
    }
}

// ---------------- 6/7: edge aggregation (R4 loop; minBlocks=6 occupancy) -----
// MODE 0: acc = sum wn * Ph[wid];  H0h = half(relu(acc*norm[dst] + b0))
// MODE 1: acc = sum wn * H0h[src]; S1h = half(acc*norm[dst])
template <int MODE>
__global__ __launch_bounds__(256, 6) void agg_k(const float* __restrict__ norm,
                                                const float* __restrict__ bias) {
    int node = (blockIdx.x * 256 + threadIdx.x) >> 5;
    if (node >= NN) return;
    int lane = threadIdx.x & 31;
    int beg = g_off[node], end = g_off[node + 1];
    const float2* tbl = (const float2*)((MODE == 0) ? g_Ph : g_H0h);

    float ax = 0.f, ay = 0.f, az = 0.f, aw = 0.f;
    int e = beg;
    for (; e + 8 <= end; e += 8) {
        int2 m[8];
#pragma unroll
        for (int j = 0; j < 8; j++) m[j] = __ldg(g_meta + e + j);
        float2 raw[8];
#pragma unroll
        for (int j = 0; j < 8; j++) {
            int idx = (MODE == 0) ? ((unsigned)m[j].x >> 17) : (m[j].x & 0x1FFFF);
            raw[j] = __ldg(tbl + idx * 32 + lane);
        }
#pragma unroll
        for (int j = 0; j < 8; j++) {
            float c = __int_as_float(m[j].y);
            float2 f0, f1; split_h2(raw[j], f0, f1);
            ax = fmaf(c, f0.x, ax); ay = fmaf(c, f0.y, ay);
            az = fmaf(c, f1.x, az); aw = fmaf(c, f1.y, aw);
        }
    }
    for (; e < end; e++) {
        int2 m = __ldg(g_meta + e);
        int idx = (MODE == 0) ? ((unsigned)m.x >> 17) : (m.x & 0x1FFFF);
        float2 raw = __ldg(tbl + idx * 32 + lane);
        float c = __int_as_float(m.y);
        float2 f0, f1; split_h2(raw, f0, f1);
        ax = fmaf(c, f0.x, ax); ay = fmaf(c, f0.y, ay);
        az = fmaf(c, f1.x, az); aw = fmaf(c, f1.y, aw);
    }
    float nd = __ldg(norm + node);
    float2 outp;
    if (MODE == 0) {
        float4 b = __ldg((const float4*)bias + lane);
        float rx = fmaxf(fmaf(ax, nd, b.x), 0.f);
        float ry = fmaxf(fmaf(ay, nd, b.y), 0.f);
        float rz = fmaxf(fmaf(az, nd, b.z), 0.f);
        float rw = fmaxf(fmaf(aw, nd, b.w), 0.f);
        *reinterpret_cast<__half2*>(&outp.x) = __floats2half2_rn(rx, ry);
        *reinterpret_cast<__half2*>(&outp.y) = __floats2half2_rn(rz, rw);
        ((float2*)g_H0h)[node * 32 + lane] = outp;
    } else {
        *reinterpret_cast<__half2*>(&outp.x) = __floats2half2_rn(ax * nd, ay * nd);
        *reinterpret_cast<__half2*>(&outp.y) = __floats2half2_rn(az * nd, aw * nd);
        ((float2*)g_S1h)[node * 32 + lane] = outp;
    }
}

// ---------------- 8: gemm1 (tensor core) + bias/relu/max-pool ----------------
__global__ __launch_bounds__(128) void gemm1_k(const float* __restrict__ bias,
                                               const int* __restrict__ gid) {
    __shared__ float sm[64][DD];
    int warp = threadIdx.x >> 5;
    int rb = blockIdx.x * 64;
    int row0 = rb + warp * 16;

    wmma::fragment<wmma::accumulator, 16, 16, 16, float> acc[8];
#pragma unroll
    for (int n = 0; n < 8; n++) wmma::fill_fragment(acc[n], 0.0f);

#pragma unroll
    for (int k = 0; k < 8; k++) {
        wmma::fragment<wmma::matrix_a, 16, 16, 16, __half, wmma::row_major> af;
        wmma::load_matrix_sync(af, g_S1h + row0 * DD + k * 16, DD);
#pragma unroll
        for (int n = 0; n < 8; n++) {
            wmma::fragment<wmma::matrix_b, 16, 16, 16, __half, wmma::row_major> bf;
            wmma::load_matrix_sync(bf, g_W1h + (k * 16) * DD + n * 16, DD);
            wmma::mma_sync(acc[n], af, bf, acc[n]);
        }
    }
#pragma unroll
    for (int n = 0; n < 8; n++)
        wmma::store_matrix_sync(&sm[warp * 16][n * 16], acc[n], DD, wmma::mem_row_major);
    __syncthreads();

    int col = threadIdx.x;
    float bv = __ldg(bias + col);
    int gfirst = __ldg(gid + rb);
    int lastrow = rb + 63; if (lastrow >= NN) lastrow = NN - 1;
    int glast = __ldg(gid + lastrow);
    if (gfirst == glast) {
        float m = 0.0f;
#pragma unroll 4
        for (int r = 0; r < 64; r++) {
            if (rb + r < NN)
                m = fmaxf(m, fmaxf(sm[r][col] + bv, 0.0f));
        }
        atomicMax((int*)&g_pool[gfirst * DD + col], __float_as_int(m));
    } else {
        for (int r = 0; r < 64; r++) {
            int row = rb + r;
            if (row < NN) {
                int gg = __ldg(gid + row);
                float v = fmaxf(sm[r][col] + bv, 0.0f);
                atomicMax((int*)&g_pool[gg * DD + col], __float_as_int(v));
            }
        }
    }
}

// ---------------- 9: head ----------------------------------------------------
__global__ void k_final(const float* __restrict__ Wout, const float* __restrict__ bout,
                        const float* __restrict__ y, float* __restrict__ out,
                        int out_size) {
    __shared__ float s_loss[NG];
    __shared__ float s_pred[NG];
    int warp = threadIdx.x >> 5;
    int lane = threadIdx.x & 31;
    if (warp < NG) {
        float4 gv = ((const float4*)g_pool)[warp * 32 + lane];
        float4 wv = __ldg((const float4*)Wout + lane);
        float d = gv.x * wv.x + gv.y * wv.y + gv.z * wv.z + gv.w * wv.w;
#pragma unroll
        for (int o = 16; o > 0; o >>= 1) d += __shfl_xor_sync(0xffffffffu, d, o);
        if (lane == 0) {
            float z = d + __ldg(bout);
            float yd = __ldg(y + warp);
            s_loss[warp] = fmaxf(z, 0.f) - z * yd + log1pf(expf(-fabsf(z)));
            s_pred[warp] = 1.f / (1.f + expf(-z));
        }
    }
    __syncthreads();
    if (threadIdx.x == 0) {
        float L = 0.f;
        for (int i = 0; i < NG; i++) L += s_loss[i];
        L *= (1.f / NG);
        if (out_size >= NG + 1) {
            out[0] = L;
            for (int i = 0; i < NG; i++) out[1 + i] = s_pred[i];
            for (int i = NG + 1; i < out_size; i++) out[i] = 0.f;
        } else if (out_size == NG) {
            for (int i = 0; i < NG; i++) out[i] = s_pred[i];
        } else {
            out[0] = L;
        }
    }
}

// ---------------- launch -----------------------------------------------------
extern "C" void kernel_launch(void* const* d_in, const int* in_sizes, int n_in,
                              void* d_out, int out_size) {
    const int*   word_ids = (const int*)d_in[0];
    const int*   esrc     = (const int*)d_in[1];
    const int*   edst     = (const int*)d_in[2];
    const float* ew       = (const float*)d_in[3];
    const float* norm     = (const float*)d_in[4];
    const int*   gid      = (const int*)d_in[5];
    const float* y        = (const float*)d_in[6];
    const float* emb      = (const float*)d_in[7];
    const float* W0       = (const float*)d_in[8];
    const float* b0       = (const float*)d_in[9];
    const float* W1       = (const float*)d_in[10];
    const float* b1       = (const float*)d_in[11];
    const float* Wout     = (const float*)d_in[12];
    const float* bout     = (const float*)d_in[13];
    float* out = (float*)d_out;

    k_zero   <<<(NPAD + 4 + 255) / 256, 256>>>(W0, W1);
    k_hist   <<<(NE + 255) / 256, 256>>>(edst);
    k_scan1  <<<NSCB, 256>>>();
    k_scan3  <<<NSCB, 256>>>();
    k_scatter<<<(NE + 255) / 256, 256>>>(esrc, edst, ew, norm, word_ids);
    gemm0_k  <<<(NV + 63) / 64, 128>>>(emb);

    agg_k<0> <<<(NN + 7) / 8, 256>>>(norm, b0);
    agg_k<1> <<<(NN + 7) / 8, 256>>>(norm, nullptr);
    gemm1_k  <<<(NN + 63) / 64, 128>>>(b1, gid);

    k_final  <<<1, 512>>>(Wout, bout, y, out, out_size);
}

// round 17
// speedup vs baseline: 1.0796x; 1.0265x over previous
#include <cuda_runtime.h>
#include <cuda_fp16.h>
#include <mma.h>
#include <math.h>

using namespace nvcuda;

#define NN 100000
#define NE 1600000
#define NV 15000
#define DD 128
#define NG 16
#define NPAD 100352                 // 98 * 1024
#define NSCB 98                     // scan blocks (1024 counts each)

// ---------------- device scratch (static: no allocations allowed) ------------
__device__ int    g_off[NPAD + 4];
__device__ int    g_cursor[NPAD + 4];
__device__ int    g_bsum[NSCB];
__device__ int2   g_meta[NE];              // {(wid<<17)|src, bits(w*norm[src])}
__device__ __half g_Ph[NV * DD];           // embeds @ W0 fp16 (L2-resident)
__device__ __half g_H0h[NN * DD];          // layer-1 output fp16
__device__ __half g_S1h[(NN + 64) * DD];   // N*A*N*H0 fp16 (padded for TC tiles)
__device__ __half g_W0h[DD * DD];
__device__ __half g_W1h[DD * DD];
__device__ float  g_pool[NG * DD];         // per-graph max (relu>=0 -> int cmp)

// ---------------- helpers ----------------------------------------------------
__device__ __forceinline__ void split_h2(float2 raw, float2& f0, float2& f1) {
    __half2 h0 = *reinterpret_cast<__half2*>(&raw.x);
    __half2 h1 = *reinterpret_cast<__half2*>(&raw.y);
    f0 = __half22float2(h0);
    f1 = __half22float2(h1);
}

// ---------------- 0: zero + W conversions ------------------------------------
__global__ void k_zero(const float* __restrict__ W0, const float* __restrict__ W1) {
    int i = blockIdx.x * 256 + threadIdx.x;
    if (i < NPAD + 4) g_off[i] = 0;
    if (i < NG * DD) g_pool[i] = 0.0f;
    if (i < DD * DD) {
        g_W0h[i] = __float2half(W0[i]);
        g_W1h[i] = __float2half(W1[i]);
    }
}

// ---------------- 1: histogram -----------------------------------------------
__global__ void k_hist(const int* __restrict__ edst) {
    int e = blockIdx.x * 256 + threadIdx.x;
    if (e < NE) atomicAdd(&g_off[edst[e]], 1);
}

// ---------------- 2: per-chunk sums ------------------------------------------
__global__ void k_scan1() {
    __shared__ int sm[256];
    int b = blockIdx.x, t = threadIdx.x;
    int4 c = ((const int4*)g_off)[b * 256 + t];
    int s = c.x + c.y + c.z + c.w;
    sm[t] = s;
    __syncthreads();
    for (int off = 128; off > 0; off >>= 1) {
        if (t < off) sm[t] += sm[t + off];
        __syncthreads();
    }
    if (t == 0) g_bsum[b] = sm[0];
}

// ---------------- 3: local scan + inline block-offset reduction --------------
__global__ void k_scan3() {
    __shared__ int sm[256];
    __shared__ int red[128];
    __shared__ int s_base;
    int b = blockIdx.x, t = threadIdx.x;

    if (t < 128) red[t] = (t < b) ? g_bsum[t] : 0;    // b <= 97 < 128
    __syncthreads();
    if (t < 64) red[t] += red[t + 64];
    __syncthreads();
    if (t < 32) {
        int v = red[t] + red[t + 32];
#pragma unroll
        for (int o = 16; o > 0; o >>= 1) v += __shfl_down_sync(0xffffffffu, v, o);
        if (t == 0) s_base = v;
    }

    int4 c = ((const int4*)g_off)[b * 256 + t];
    int s = c.x + c.y + c.z + c.w;
    sm[t] = s;
    __syncthreads();
    for (int off = 1; off < 256; off <<= 1) {
        int u = (t >= off) ? sm[t - off] : 0;
        __syncthreads();
        sm[t] += u;
        __syncthreads();
    }
    int base = s_base + sm[t] - s;
    int4 o;
    o.x = base;
    o.y = base + c.x;
    o.z = o.y + c.y;
    o.w = o.z + c.z;
    ((int4*)g_off)[b * 256 + t] = o;
    ((int4*)g_cursor)[b * 256 + t] = o;
}

// ---------------- 4: scatter (standalone, low-footprint) ---------------------
__global__ void k_scatter(const int* __restrict__ esrc, const int* __restrict__ edst,
                          const float* __restrict__ ew, const float* __restrict__ norm,
                          const int* __restrict__ word_ids) {
    int e = blockIdx.x * 256 + threadIdx.x;
    if (e >= NE) return;
    int d = edst[e];
    int s = esrc[e];
    int pos = atomicAdd(&g_cursor[d], 1);
    float wn = ew[e] * __ldg(&norm[s]);
    int packed = s | (__ldg(&word_ids[s]) << 17);   // src < 2^17, wid < 2^14
    g_meta[pos] = make_int2(packed, __float_as_int(wn));
}

// ---------------- 5: gemm0 -- Ph = half(emb @ W0), inline fp32->fp16 ---------
__global__ __launch_bounds__(128) void gemm0_k(const float* __restrict__ emb) {
    __shared__ __half Ah[64 * DD];   // 16 KB
    __shared__ float St[64 * 32];    // 8 KB staging
    int rb = blockIdx.x * 64;
    for (int i = threadIdx.x; i < 64 * DD; i += 128) {
        int row = rb + (i >> 7);
        Ah[i] = (row < NV) ? __float2half(emb[row * DD + (i & 127)]) : __half(0.f);
    }
    __syncthreads();

    int warp = threadIdx.x >> 5;
    wmma::fragment<wmma::accumulator, 16, 16, 16, float> acc[8];
#pragma unroll
    for (int n = 0; n < 8; n++) wmma::fill_fragment(acc[n], 0.0f);
#pragma unroll
    for (int k = 0; k < 8; k++) {
        wmma::fragment<wmma::matrix_a, 16, 16, 16, __half, wmma::row_major> af;
        wmma::load_matrix_sync(af, Ah + (warp * 16) * DD + k * 16, DD);
#pragma unroll
        for (int n = 0; n < 8; n++) {
            wmma::fragment<wmma::matrix_b, 16, 16, 16, __half, wmma::row_major> bf;
            wmma::load_matrix_sync(bf, g_W0h + (k * 16) * DD + n * 16, DD);
            wmma::mma_sync(acc[n], af, bf, acc[n]);
        }
    }
    __syncthreads();
#pragma unroll
    for (int n = 0; n < 8; n += 2) {
        wmma::store_matrix_sync(&St[warp * 16 * 32 + 0],  acc[n],     32, wmma::mem_row_major);
        wmma::store_matrix_sync(&St[warp * 16 * 32 + 16], acc[n + 1], 32, wmma::mem_row_major);
        __syncwarp();
        int lane = threadIdx.x & 31;
#pragma unroll
        for (int r = 0; r < 16; r++) {
            int row = rb + warp * 16 + r;
            if (row < NV) {
                float v = St[warp * 16 * 32 + r * 32 + lane];
                g_Ph[row * DD + n * 16 + lane] = __float2half(v);
            }
        }
        __syncwarp();
    }
}

// ---------------- 6/7: edge aggregation (warp per node; tuned R4 loop) -------
// MODE 0: acc = sum wn * Ph[wid];  H0h = half(relu(acc*norm[dst] + b0))
// MODE 1: acc = sum wn * H0h[src]; S1h = half(acc*norm[dst])
template <int MODE>
__global__ __launch_bounds__(256) void agg_k(const float* __restrict__ norm,
                                             const float* __restrict__ bias) {
    int node = (blockIdx.x * 256 + threadIdx.x) >> 5;
    if (node >= NN) return;
    int lane = threadIdx.x & 31;
    int beg = g_off[node], end = g_off[node + 1];
    const float2* tbl = (const float2*)((MODE == 0) ? g_Ph : g_H0h);

    float ax = 0.f, ay = 0.f, az = 0.f, aw = 0.f;
    int e = beg;
    for (; e + 8 <= end; e += 8) {
        int2 m[8];
#pragma unroll
        for (int j = 0; j < 8; j++) m[j] = __ldg(g_meta + e + j);
        float2 raw[8];
#pragma unroll
        for (int j = 0; j < 8; j++) {
            int idx = (MODE == 0) ? ((unsigned)m[j].x >> 17) : (m[j].x & 0x1FFFF);
            raw[j] = __ldg(tbl + idx * 32 + lane);
        }
#pragma unroll
        for (int j = 0; j < 8; j++) {
            float c = __int_as_float(m[j].y);
            float2 f0, f1; split_h2(raw[j], f0, f1);
            ax = fmaf(c, f0.x, ax); ay = fmaf(c, f0.y, ay);
            az = fmaf(c, f1.x, az); aw = fmaf(c, f1.y, aw);
        }
    }
    for (; e < end; e++) {
        int2 m = __ldg(g_meta + e);
        int idx = (MODE == 0) ? ((unsigned)m.x >> 17) : (m.x & 0x1FFFF);
        float2 raw = __ldg(tbl + idx * 32 + lane);
        float c = __int_as_float(m.y);
        float2 f0, f1; split_h2(raw, f0, f1);
        ax = fmaf(c, f0.x, ax); ay = fmaf(c, f0.y, ay);
        az = fmaf(c, f1.x, az); aw = fmaf(c, f1.y, aw);
    }
    float nd = __ldg(norm + node);
    float2 outp;
    if (MODE == 0) {
        float4 b = __ldg((const float4*)bias + lane);
        float rx = fmaxf(fmaf(ax, nd, b.x), 0.f);
        float ry = fmaxf(fmaf(ay, nd, b.y), 0.f);
        float rz = fmaxf(fmaf(az, nd, b.z), 0.f);
        float rw = fmaxf(fmaf(aw, nd, b.w), 0.f);
        *reinterpret_cast<__half2*>(&outp.x) = __floats2half2_rn(rx, ry);
        *reinterpret_cast<__half2*>(&outp.y) = __floats2half2_rn(rz, rw);
        ((float2*)g_H0h)[node * 32 + lane] = outp;
    } else {
        *reinterpret_cast<__half2*>(&outp.x) = __floats2half2_rn(ax * nd, ay * nd);
        *reinterpret_cast<__half2*>(&outp.y) = __floats2half2_rn(az * nd, aw * nd);
        ((float2*)g_S1h)[node * 32 + lane] = outp;
    }
}

// ---------------- 8: gemm1 (tensor core) + bias/relu/max-pool ----------------
__global__ __launch_bounds__(128) void gemm1_k(const float* __restrict__ bias,
                                               const int* __restrict__ gid) {
    __shared__ float sm[64][DD];
    int warp = threadIdx.x >> 5;
    int rb = blockIdx.x * 64;
    int row0 = rb + warp * 16;

    wmma::fragment<wmma::accumulator, 16, 16, 16, float> acc[8];
#pragma unroll
    for (int n = 0; n < 8; n++) wmma::fill_fragment(acc[n], 0.0f);

#pragma unroll
    for (int k = 0; k < 8; k++) {
        wmma::fragment<wmma::matrix_a, 16, 16, 16, __half, wmma::row_major> af;
        wmma::load_matrix_sync(af, g_S1h + row0 * DD + k * 16, DD);
#pragma unroll
        for (int n = 0; n < 8; n++) {
            wmma::fragment<wmma::matrix_b, 16, 16, 16, __half, wmma::row_major> bf;
            wmma::load_matrix_sync(bf, g_W1h + (k * 16) * DD + n * 16, DD);
            wmma::mma_sync(acc[n], af, bf, acc[n]);
        }
    }
#pragma unroll
    for (int n = 0; n < 8; n++)
        wmma::store_matrix_sync(&sm[warp * 16][n * 16], acc[n], DD, wmma::mem_row_major);
    __syncthreads();

    int col = threadIdx.x;
    float bv = __ldg(bias + col);
    int gfirst = __ldg(gid + rb);
    int lastrow = rb + 63; if (lastrow >= NN) lastrow = NN - 1;
    int glast = __ldg(gid + lastrow);
    if (gfirst == glast) {
        float m = 0.0f;
#pragma unroll 4
        for (int r = 0; r < 64; r++) {
            if (rb + r < NN)
                m = fmaxf(m, fmaxf(sm[r][col] + bv, 0.0f));
        }
        atomicMax((int*)&g_pool[gfirst * DD + col], __float_as_int(m));
    } else {
        for (int r = 0; r < 64; r++) {
            int row = rb + r;
            if (row < NN) {
                int gg = __ldg(gid + row);
                float v = fmaxf(sm[r][col] + bv, 0.0f);
                atomicMax((int*)&g_pool[gg * DD + col], __float_as_int(v));
            }
        }
    }
}

// ---------------- 9: head ----------------------------------------------------
__global__ void k_final(const float* __restrict__ Wout, const float* __restrict__ bout,
                        const float* __restrict__ y, float* __restrict__ out,
                        int out_size) {
    __shared__ float s_loss[NG];
    __shared__ float s_pred[NG];
    int warp = threadIdx.x >> 5;
    int lane = threadIdx.x & 31;
    if (warp < NG) {
        float4 gv = ((const float4*)g_pool)[warp * 32 + lane];
        float4 wv = __ldg((const float4*)Wout + lane);
        float d = gv.x * wv.x + gv.y * wv.y + gv.z * wv.z + gv.w * wv.w;
#pragma unroll
        for (int o = 16; o > 0; o >>= 1) d += __shfl_xor_sync(0xffffffffu, d, o);
        if (lane == 0) {
            float z = d + __ldg(bout);
            float yd = __ldg(y + warp);
            s_loss[warp] = fmaxf(z, 0.f) - z * yd + log1pf(expf(-fabsf(z)));
            s_pred[warp] = 1.f / (1.f + expf(-z));
        }
    }
    __syncthreads();
    if (threadIdx.x == 0) {
        float L = 0.f;
        for (int i = 0; i < NG; i++) L += s_loss[i];
        L *= (1.f / NG);
        if (out_size >= NG + 1) {
            out[0] = L;
            for (int i = 0; i < NG; i++) out[1 + i] = s_pred[i];
            for (int i = NG + 1; i < out_size; i++) out[i] = 0.f;
        } else if (out_size == NG) {
            for (int i = 0; i < NG; i++) out[i] = s_pred[i];
        } else {
            out[0] = L;
        }
    }
}

// ---------------- launch -----------------------------------------------------
extern "C" void kernel_launch(void* const* d_in, const int* in_sizes, int n_in,
                              void* d_out, int out_size) {
    const int*   word_ids = (const int*)d_in[0];
    const int*   esrc     = (const int*)d_in[1];
    const int*   edst     = (const int*)d_in[2];
    const float* ew       = (const float*)d_in[3];
    const float* norm     = (const float*)d_in[4];
    const int*   gid      = (const int*)d_in[5];
    const float* y        = (const float*)d_in[6];
    const float* emb      = (const float*)d_in[7];
    const float* W0       = (const float*)d_in[8];
    const float* b0       = (const float*)d_in[9];
    const float* W1       = (const float*)d_in[10];
    const float* b1       = (const float*)d_in[11];
    const float* Wout     = (const float*)d_in[12];
    const float* bout     = (const float*)d_in[13];
    float* out = (float*)d_out;

    k_zero   <<<(NPAD + 4 + 255) / 256, 256>>>(W0, W1);
    k_hist   <<<(NE + 255) / 256, 256>>>(edst);
    k_scan1  <<<NSCB, 256>>>();
    k_scan3  <<<NSCB, 256>>>();
    k_scatter<<<(NE + 255) / 256, 256>>>(esrc, edst, ew, norm, word_ids);
    gemm0_k  <<<(NV + 63) / 64, 128>>>(emb);

    agg_k<0> <<<(NN + 7) / 8, 256>>>(norm, b0);
    agg_k<1> <<<(NN + 7) / 8, 256>>>(norm, nullptr);
    gemm1_k  <<<(NN + 63) / 64, 128>>>(b1, gid);

    k_final  <<<1, 512>>>(Wout, bout, y, out, out_size);
}